// round 6
// baseline (speedup 1.0000x reference)
#include <cuda_runtime.h>
#include <cstdint>

#define BB 64
#define PP 256
#define NN 1000
typedef unsigned long long ull;

__device__ float g_Kt[BB * 128 * NN];   // [b][h][d][n]
__device__ float g_V [BB * NN * 128];   // [b][n][h*16+d]
__device__ float g_Q [BB * PP * 128];

// ---- f32x2 / memory helpers ----
__device__ __forceinline__ ull ffma2(ull a, ull b, ull c) {
    ull d; asm("fma.rn.f32x2 %0,%1,%2,%3;" : "=l"(d) : "l"(a), "l"(b), "l"(c)); return d;
}
__device__ __forceinline__ ull fmul2(ull a, ull b) {
    ull d; asm("mul.rn.f32x2 %0,%1,%2;" : "=l"(d) : "l"(a), "l"(b)); return d;
}
__device__ __forceinline__ ull fadd2(ull a, ull b) {
    ull d; asm("add.rn.f32x2 %0,%1,%2;" : "=l"(d) : "l"(a), "l"(b)); return d;
}
__device__ __forceinline__ ull pack2(float lo, float hi) {
    ull d; asm("mov.b64 %0,{%1,%2};" : "=l"(d) : "f"(lo), "f"(hi)); return d;
}
__device__ __forceinline__ float hadd2(ull a) {
    float lo, hi; asm("mov.b64 {%0,%1},%2;" : "=f"(lo), "=f"(hi) : "l"(a)); return lo + hi;
}
__device__ __forceinline__ void unpack2(ull a, float& lo, float& hi) {
    asm("mov.b64 {%0,%1},%2;" : "=f"(lo), "=f"(hi) : "l"(a));
}
__device__ __forceinline__ void lds2x64(const float* p, ull& a, ull& b) {
    uint32_t ad = (uint32_t)__cvta_generic_to_shared(p);
    asm("ld.shared.v2.b64 {%0,%1},[%2];" : "=l"(a), "=l"(b) : "r"(ad));
}
__device__ __forceinline__ ull lds64(const float* p) {
    uint32_t ad = (uint32_t)__cvta_generic_to_shared(p);
    ull a; asm("ld.shared.b64 %0,[%1];" : "=l"(a) : "r"(ad)); return a;
}
__device__ __forceinline__ void sts64(float* p, ull v) {
    uint32_t ad = (uint32_t)__cvta_generic_to_shared(p);
    asm volatile("st.shared.b64 [%0],%1;" :: "r"(ad), "l"(v));
}
__device__ __forceinline__ void ldg2x64(const float* p, ull& a, ull& b) {
    asm("ld.global.nc.v2.b64 {%0,%1},[%2];" : "=l"(a), "=l"(b) : "l"(p));
}
__device__ __forceinline__ void cp16(float* dst, const float* src) {
    uint32_t d = (uint32_t)__cvta_generic_to_shared(dst);
    asm volatile("cp.async.cg.shared.global [%0],[%1],16;" :: "r"(d), "l"(src));
}
__device__ __forceinline__ void cp_commit() { asm volatile("cp.async.commit_group;"); }
template <int N> __device__ __forceinline__ void cp_wait() {
    asm volatile("cp.async.wait_group %0;" :: "n"(N));
}

// ---------------------------------------------------------------------------
// K/V projection (R4-style compute).  block = (b, 32-node chunk), 256 threads.
// thread = (mat, row-half, col-pair): 16 rows x 2 cols, f32x2 along K.
// K written TRANSPOSED to g_Kt[b][h][d][n]; V written row-major.
// ---------------------------------------------------------------------------
__global__ __launch_bounds__(256) void kv_proj(const float* __restrict__ enc,
                                               const float* __restrict__ Wk,
                                               const float* __restrict__ Wv) {
    __shared__ float xs[32 * 128];
    int t = threadIdx.x;
    int b = blockIdx.x >> 5;
    int n0 = (blockIdx.x & 31) * 32;
    int nvalid = NN - n0; if (nvalid > 32) nvalid = 32;

    const float4* src = (const float4*)(enc + ((size_t)b * NN + n0) * 128);
    float4* xs4 = (float4*)xs;
#pragma unroll
    for (int i = t; i < 1024; i += 256) {
        if ((i >> 5) < nvalid) xs4[i] = src[i];
    }
    __syncthreads();

    int mat = t >> 7, rh = (t >> 6) & 1, cp = t & 63;
    const float* W = mat ? Wv : Wk;
    const float* xb = xs + rh * 2048;

    ull acc[32];
#pragma unroll
    for (int i = 0; i < 32; i++) acc[i] = 0ull;

#pragma unroll 2
    for (int k = 0; k < 128; k += 2) {
        ull w0 = pack2(W[k * 128 + cp], W[(k + 1) * 128 + cp]);
        ull w1 = pack2(W[k * 128 + cp + 64], W[(k + 1) * 128 + cp + 64]);
#pragma unroll
        for (int r = 0; r < 16; r++) {
            ull x = lds64(xb + r * 128 + k);
            acc[r]      = ffma2(x, w0, acc[r]);
            acc[16 + r] = ffma2(x, w1, acc[16 + r]);
        }
    }

    if (mat == 0) {
        // K -> transposed [b][ (h*16+d) ][ n ]
        float* K1 = g_Kt + ((size_t)b * 128 + cp) * NN + n0;
        float* K2 = g_Kt + ((size_t)b * 128 + cp + 64) * NN + n0;
#pragma unroll
        for (int r = 0; r < 16; r++) {
            int n = rh * 16 + r;
            if (n < nvalid) {
                K1[n] = hadd2(acc[r]);
                K2[n] = hadd2(acc[16 + r]);
            }
        }
    } else {
#pragma unroll
        for (int r = 0; r < 16; r++) {
            int n = rh * 16 + r;
            if (n < nvalid) {
                float* vr = g_V + ((size_t)b * NN + n0 + n) * 128;
                vr[cp]      = hadd2(acc[r]);
                vr[cp + 64] = hadd2(acc[16 + r]);
            }
        }
    }
}

// ---------------------------------------------------------------------------
// Q projection: 16 rows/block, 256 threads.
// ---------------------------------------------------------------------------
__global__ __launch_bounds__(256) void q_proj(const float* __restrict__ last,
                                              const float* __restrict__ attr,
                                              const float* __restrict__ Wq) {
    __shared__ float xs[16 * 132];
    int row0 = blockIdx.x * 16;
    int t = threadIdx.x;
#pragma unroll
    for (int i = t; i < 2048; i += 256) {
        int r = i >> 7, c = i & 127;
        xs[r * 132 + c] = last[(size_t)(row0 + r) * 128 + c];
    }
    if (t < 16) xs[t * 132 + 128] = attr[row0 + t];
    __syncthreads();

    int rh = t >> 7, col = t & 127;
    const float* xr = xs + rh * 8 * 132;
    float acc[8] = {0, 0, 0, 0, 0, 0, 0, 0};
#pragma unroll 4
    for (int in = 0; in < 129; in++) {
        float w = Wq[in * 128 + col];
#pragma unroll
        for (int r = 0; r < 8; r++) acc[r] += xr[r * 132 + in] * w;
    }
#pragma unroll
    for (int r = 0; r < 8; r++)
        g_Q[(size_t)(row0 + rh * 8 + r) * 128 + col] = acc[r];
}

// ---------------------------------------------------------------------------
// Fused attention + Wo + tanh scoring + final softmax.
// block = (b, 16-query tile), 256 threads, cp.async double-buffered.
// Phase A: warp = head h; lane: pl = (lane>>1), half = lane&1 (n-half).
//   Scores accumulated as f32x2 pairs over n (K transposed in smem).
// smem floats: mh 2112 | inv 16 | out 2112 | work 18816  (total 92224 B)
//   phase A work: kT0/kT1 (128 rows x 36) | v0/v1 (32 x 132) | m0/m1 (16 x 36)
//   phase B work: enc0/enc1 (64 x 132)
// ---------------------------------------------------------------------------
__global__ __launch_bounds__(256, 2) void attn_kernel(
        const float* __restrict__ enc, const float* __restrict__ mask,
        const float* __restrict__ Wo, const float* __restrict__ bo,
        float* __restrict__ probs) {
    extern __shared__ float sm[];
    float* mh_s  = sm;
    float* inv_s = sm + 2112;
    float* out_s = sm + 2128;
    float* work  = sm + 4240;

    int t = threadIdx.x;
    int b = blockIdx.x >> 4;
    int p0 = (blockIdx.x & 15) * 16;

    int h = t >> 5, pl = (t >> 1) & 15, half = t & 1;

    const float* Ktb = g_Kt + (size_t)b * 128 * NN;
    const float* Vb  = g_V  + (size_t)b * NN * 128;
    const float* Mb  = mask + (size_t)(b * PP + p0) * NN;

    auto stageA = [&](int chunk) {
        int buf = chunk & 1;
        int base = chunk * 32;
        int nv = NN - base; if (nv > 32) nv = 32;
        float* kd = work + buf * 4608;
        float* vd = work + 9216 + buf * 4224;
        float* md = work + 17664 + buf * 576;
        // kT: 128 rows x 8 segs of 4 n
#pragma unroll
        for (int j = 0; j < 4; j++) {
            int i = t + j * 256;
            int r = i >> 3, seg = i & 7;
            if (seg * 4 < nv)
                cp16(kd + r * 36 + seg * 4, Ktb + (size_t)r * NN + base + seg * 4);
        }
        // V: 32 rows x 32 segs
#pragma unroll
        for (int j = 0; j < 4; j++) {
            int i = t + j * 256;
            int n = i >> 5, seg = i & 31;
            if (n < nv)
                cp16(vd + n * 132 + seg * 4, Vb + (size_t)(base + n) * 128 + seg * 4);
        }
        if (t < 128) {
            int p = t >> 3, seg = t & 7;
            if (seg * 4 < nv)
                cp16(md + p * 36 + seg * 4, Mb + (size_t)p * NN + base + seg * 4);
        }
    };
    auto stageB = [&](int chunk) {
        int buf = chunk & 1;
        int base = chunk * 64;
        int nv = NN - base; if (nv > 64) nv = 64;
        float* ed = work + buf * 8448;
        const float* Eb = enc + (size_t)b * NN * 128;
#pragma unroll
        for (int j = 0; j < 8; j++) {
            int i = t + j * 256;
            int n = i >> 5, seg = i & 31;
            if (n < nv)
                cp16(ed + n * 132 + seg * 4, Eb + (size_t)(base + n) * 128 + seg * 4);
        }
    };

    // q prepacked (0.25 scale folded), duplicated lanes
    ull qpk[16];
    {
        const float4* qp = (const float4*)(g_Q + (size_t)(b * PP + p0 + pl) * 128 + h * 16);
#pragma unroll
        for (int j = 0; j < 4; j++) {
            float4 qv = qp[j];
            qpk[4 * j]     = pack2(qv.x * 0.25f, qv.x * 0.25f);
            qpk[4 * j + 1] = pack2(qv.y * 0.25f, qv.y * 0.25f);
            qpk[4 * j + 2] = pack2(qv.z * 0.25f, qv.z * 0.25f);
            qpk[4 * j + 3] = pack2(qv.w * 0.25f, qv.w * 0.25f);
        }
    }

    float m = -1e30f, l = 0.f;
    ull acc[8];
#pragma unroll
    for (int j = 0; j < 8; j++) acc[j] = 0ull;

    stageA(0); cp_commit();
    stageA(1); cp_commit();

    // ---- phase A ----
    for (int c = 0; c < 32; c++) {
        if (c == 31) cp_wait<0>(); else cp_wait<1>();
        __syncthreads();

        int buf = c & 1;
        int base = c * 32;
        int nv = NN - base; if (nv > 32) nv = 32;
        const float* k_s    = work + buf * 4608;
        const float* v_s    = work + 9216 + buf * 4224;
        const float* mask_s = work + 17664 + buf * 576;

        // scores as f32x2 pairs over this thread's 16 contiguous n
        ull sp[8];
        {
            const float* mp = mask_s + pl * 36 + half * 16;
            lds2x64(mp,      sp[0], sp[1]);
            lds2x64(mp + 4,  sp[2], sp[3]);
            lds2x64(mp + 8,  sp[4], sp[5]);
            lds2x64(mp + 12, sp[6], sp[7]);
        }
        const float* kb = k_s + (h * 16) * 36 + half * 16;
#pragma unroll
        for (int d = 0; d < 16; d++) {
            const float* kp = kb + d * 36;
            ull k0, k1, k2, k3, k4, k5, k6, k7;
            lds2x64(kp,      k0, k1);
            lds2x64(kp + 4,  k2, k3);
            lds2x64(kp + 8,  k4, k5);
            lds2x64(kp + 12, k6, k7);
            ull q = qpk[d];
            sp[0] = ffma2(q, k0, sp[0]); sp[1] = ffma2(q, k1, sp[1]);
            sp[2] = ffma2(q, k2, sp[2]); sp[3] = ffma2(q, k3, sp[3]);
            sp[4] = ffma2(q, k4, sp[4]); sp[5] = ffma2(q, k5, sp[5]);
            sp[6] = ffma2(q, k6, sp[6]); sp[7] = ffma2(q, k7, sp[7]);
        }

        float s[16];
#pragma unroll
        for (int j = 0; j < 8; j++) unpack2(sp[j], s[2 * j], s[2 * j + 1]);
        if (nv < 32) {
#pragma unroll
            for (int i = 0; i < 16; i++)
                if (half * 16 + i >= nv) s[i] = -1e30f;
        }

        float cmax = s[0];
#pragma unroll
        for (int i = 1; i < 16; i++) cmax = fmaxf(cmax, s[i]);
        cmax = fmaxf(cmax, __shfl_xor_sync(0xFFFFFFFFu, cmax, 1));
        float nm = fmaxf(m, cmax);
        float r = __expf(m - nm);
        m = nm;
        float lsum = 0.f;
#pragma unroll
        for (int i = 0; i < 16; i++) { s[i] = __expf(s[i] - m); lsum += s[i]; }
        l = l * r + lsum;
        ull rr = pack2(r, r);
#pragma unroll
        for (int j = 0; j < 8; j++) acc[j] = fmul2(acc[j], rr);

#pragma unroll
        for (int i = 0; i < 16; i++) {
            int n = half * 16 + i;
            const float* vp = v_s + n * 132 + h * 16;
            ull v0, v1, v2, v3, v4, v5, v6, v7;
            lds2x64(vp,      v0, v1);
            lds2x64(vp + 4,  v2, v3);
            lds2x64(vp + 8,  v4, v5);
            lds2x64(vp + 12, v6, v7);
            ull w = pack2(s[i], s[i]);
            acc[0] = ffma2(w, v0, acc[0]); acc[1] = ffma2(w, v1, acc[1]);
            acc[2] = ffma2(w, v2, acc[2]); acc[3] = ffma2(w, v3, acc[3]);
            acc[4] = ffma2(w, v4, acc[4]); acc[5] = ffma2(w, v5, acc[5]);
            acc[6] = ffma2(w, v6, acc[6]); acc[7] = ffma2(w, v7, acc[7]);
        }
        __syncthreads();
        if (c + 2 < 32) { stageA(c + 2); cp_commit(); }
    }

    // merge n-half partners, normalize, write out_s
    float lt = l + __shfl_xor_sync(0xFFFFFFFFu, l, 1);
    float inv = 1.f / lt;
    ull iv = pack2(inv, inv);
#pragma unroll
    for (int j = 0; j < 8; j++) {
        ull o = __shfl_xor_sync(0xFFFFFFFFu, acc[j], 1);
        acc[j] = fmul2(fadd2(acc[j], o), iv);
    }
    {
        float* op = out_s + pl * 132 + h * 16 + half * 8;
#pragma unroll
        for (int jj = 0; jj < 4; jj++) sts64(op + 2 * jj, acc[half * 4 + jj]);
    }
    __syncthreads();

    stageB(0); cp_commit();
    stageB(1); cp_commit();

    // Wo GEMM (overlaps the enc prefetch)
    {
        int p = t >> 4;
        int eg = (t & 15) * 8;
        ull a0, a1, a2, a3;
        ldg2x64(bo + eg, a0, a1);
        ldg2x64(bo + eg + 4, a2, a3);
        const float* op = out_s + p * 132;
#pragma unroll 4
        for (int in = 0; in < 128; in++) {
            float x = op[in];
            ull xx = pack2(x, x);
            ull w0, w1, w2, w3;
            ldg2x64(Wo + in * 128 + eg, w0, w1);
            ldg2x64(Wo + in * 128 + eg + 4, w2, w3);
            a0 = ffma2(xx, w0, a0); a1 = ffma2(xx, w1, a1);
            a2 = ffma2(xx, w2, a2); a3 = ffma2(xx, w3, a3);
        }
        float* mp = mh_s + p * 132 + eg;
        sts64(mp, a0); sts64(mp + 2, a1); sts64(mp + 4, a2); sts64(mp + 6, a3);
    }

    // ---- phase B: tanh-clipped scoring, 16 chunks of 64 nodes ----
    int pg = t >> 5, ng = t & 31;
    float rs0 = 0.f, rs1 = 0.f;
    float* pout = probs + (size_t)(b * PP + p0) * NN;
    const float inv_se = 0.08838834764831845f;
    const float* mrow0 = mh_s + (2 * pg) * 132;
    const float* mrow1 = mrow0 + 132;

    for (int c = 0; c < 16; c++) {
        if (c == 15) cp_wait<0>(); else cp_wait<1>();
        __syncthreads();

        int buf = c & 1;
        int base = c * 64;
        int nv = NN - base; if (nv > 64) nv = 64;
        const float* e_s = work + buf * 8448;

        ull a[2][2];
#pragma unroll
        for (int pp = 0; pp < 2; pp++)
#pragma unroll
            for (int j = 0; j < 2; j++) a[pp][j] = 0ull;

#pragma unroll 4
        for (int k = 0; k < 128; k += 4) {
            ull m00, m01, m10, m11;
            lds2x64(mrow0 + k, m00, m01);
            lds2x64(mrow1 + k, m10, m11);
#pragma unroll
            for (int j = 0; j < 2; j++) {
                const float* ep = e_s + (ng + 32 * j) * 132 + k;
                ull e0, e1; lds2x64(ep, e0, e1);
                a[0][j] = ffma2(m00, e0, a[0][j]);
                a[0][j] = ffma2(m01, e1, a[0][j]);
                a[1][j] = ffma2(m10, e0, a[1][j]);
                a[1][j] = ffma2(m11, e1, a[1][j]);
            }
        }
#pragma unroll
        for (int j = 0; j < 2; j++) {
            int n = ng + 32 * j;
            if (n < nv) {
#pragma unroll
                for (int pp = 0; pp < 2; pp++) {
                    int p = 2 * pg + pp;
                    float sd = hadd2(a[pp][j]);
                    float x = sd * inv_se;
                    x = fminf(fmaxf(x, -30.f), 30.f);
                    float ex = __expf(-2.f * x);
                    float th = __fdividef(1.f - ex, 1.f + ex);
                    float lg = 10.f * th + Mb[(size_t)p * NN + base + n];
                    float w = __expf(lg - 10.f);
                    if (pp) rs1 += w; else rs0 += w;
                    pout[(size_t)p * NN + base + n] = w;
                }
            }
        }
        __syncthreads();
        if (c + 2 < 16) { stageB(c + 2); cp_commit(); }
    }

#pragma unroll
    for (int off = 16; off; off >>= 1) {
        rs0 += __shfl_xor_sync(0xFFFFFFFFu, rs0, off);
        rs1 += __shfl_xor_sync(0xFFFFFFFFu, rs1, off);
    }
    if (ng == 0) {
        inv_s[2 * pg]     = 1.f / rs0;
        inv_s[2 * pg + 1] = 1.f / rs1;
    }
    __syncthreads();
#pragma unroll
    for (int p = 0; p < 16; p++) {
        float ivp = inv_s[p];
        for (int i = t; i < NN; i += 256)
            pout[(size_t)p * NN + i] *= ivp;
    }
}

// ---------------------------------------------------------------------------
extern "C" void kernel_launch(void* const* d_in, const int* in_sizes, int n_in,
                              void* d_out, int out_size) {
    const float* enc  = (const float*)d_in[0];
    const float* last = (const float*)d_in[1];
    const float* attr = (const float*)d_in[2];
    const float* mask = (const float*)d_in[3];
    const float* Wq   = (const float*)d_in[4];
    const float* Wk   = (const float*)d_in[5];
    const float* Wv   = (const float*)d_in[6];
    const float* Wo   = (const float*)d_in[7];
    const float* bo   = (const float*)d_in[8];
    float* out = (float*)d_out;

    cudaFuncSetAttribute(attn_kernel,
                         cudaFuncAttributeMaxDynamicSharedMemorySize, 92224);

    kv_proj<<<2048, 256>>>(enc, Wk, Wv);
    q_proj<<<1024, 256>>>(last, attr, Wq);
    attn_kernel<<<1024, 256, 92224>>>(enc, mask, Wo, bo, out);
}

// round 7
// speedup vs baseline: 1.1844x; 1.1844x over previous
#include <cuda_runtime.h>
#include <cstdint>

#define BB 64
#define PP 256
#define NN 1000
typedef unsigned long long ull;

__device__ float g_K[BB * NN * 128];
__device__ float g_V[BB * NN * 128];
__device__ float g_Q[BB * PP * 128];

// ---- f32x2 / memory helpers ----
__device__ __forceinline__ ull ffma2(ull a, ull b, ull c) {
    ull d; asm("fma.rn.f32x2 %0,%1,%2,%3;" : "=l"(d) : "l"(a), "l"(b), "l"(c)); return d;
}
__device__ __forceinline__ ull fmul2(ull a, ull b) {
    ull d; asm("mul.rn.f32x2 %0,%1,%2;" : "=l"(d) : "l"(a), "l"(b)); return d;
}
__device__ __forceinline__ ull pack2(float lo, float hi) {
    ull d; asm("mov.b64 %0,{%1,%2};" : "=l"(d) : "f"(lo), "f"(hi)); return d;
}
__device__ __forceinline__ float hadd2(ull a) {
    float lo, hi; asm("mov.b64 {%0,%1},%2;" : "=f"(lo), "=f"(hi) : "l"(a)); return lo + hi;
}
__device__ __forceinline__ void lds2x64(const float* p, ull& a, ull& b) {
    uint32_t ad = (uint32_t)__cvta_generic_to_shared(p);
    asm("ld.shared.v2.b64 {%0,%1},[%2];" : "=l"(a), "=l"(b) : "r"(ad));
}
__device__ __forceinline__ ull lds64(const float* p) {
    uint32_t ad = (uint32_t)__cvta_generic_to_shared(p);
    ull a; asm("ld.shared.b64 %0,[%1];" : "=l"(a) : "r"(ad)); return a;
}
__device__ __forceinline__ void sts64(float* p, ull v) {
    uint32_t ad = (uint32_t)__cvta_generic_to_shared(p);
    asm volatile("st.shared.b64 [%0],%1;" :: "r"(ad), "l"(v));
}
__device__ __forceinline__ void sts128z(float* p) {
    uint32_t ad = (uint32_t)__cvta_generic_to_shared(p);
    asm volatile("st.shared.v4.b32 [%0],{%1,%1,%1,%1};" :: "r"(ad), "r"(0));
}
__device__ __forceinline__ void sts32(float* p, float v) {
    uint32_t ad = (uint32_t)__cvta_generic_to_shared(p);
    asm volatile("st.shared.b32 [%0],%1;" :: "r"(ad), "f"(v));
}
__device__ __forceinline__ void ldg2x64(const float* p, ull& a, ull& b) {
    asm("ld.global.nc.v2.b64 {%0,%1},[%2];" : "=l"(a), "=l"(b) : "l"(p));
}
__device__ __forceinline__ void cp16(float* dst, const float* src) {
    uint32_t d = (uint32_t)__cvta_generic_to_shared(dst);
    asm volatile("cp.async.cg.shared.global [%0],[%1],16;" :: "r"(d), "l"(src));
}
__device__ __forceinline__ void cp4(float* dst, const float* src) {
    uint32_t d = (uint32_t)__cvta_generic_to_shared(dst);
    asm volatile("cp.async.ca.shared.global [%0],[%1],4;" :: "r"(d), "l"(src));
}
__device__ __forceinline__ void cp_commit() { asm volatile("cp.async.commit_group;"); }
template <int N> __device__ __forceinline__ void cp_wait() {
    asm volatile("cp.async.wait_group %0;" :: "n"(N));
}

// ---------------------------------------------------------------------------
// K/V projection (R4 form, measured 119us). 32 rows/block, 256 threads.
// ---------------------------------------------------------------------------
__global__ __launch_bounds__(256) void kv_proj(const float* __restrict__ enc,
                                               const float* __restrict__ Wk,
                                               const float* __restrict__ Wv) {
    __shared__ float xs[32 * 128];
    int t = threadIdx.x;
    int row0 = blockIdx.x * 32;
    const float4* src = (const float4*)(enc + (size_t)row0 * 128);
    float4* xs4 = (float4*)xs;
#pragma unroll
    for (int i = t; i < 1024; i += 256) xs4[i] = src[i];
    __syncthreads();

    int mat = t >> 7, rh = (t >> 6) & 1, cp = t & 63;
    const float* W = mat ? Wv : Wk;
    float* out = mat ? g_V : g_K;
    const float* xb = xs + rh * 2048;

    ull acc[32];
#pragma unroll
    for (int i = 0; i < 32; i++) acc[i] = 0ull;

#pragma unroll 2
    for (int k = 0; k < 128; k += 2) {
        ull w0 = pack2(W[k * 128 + cp], W[(k + 1) * 128 + cp]);
        ull w1 = pack2(W[k * 128 + cp + 64], W[(k + 1) * 128 + cp + 64]);
#pragma unroll
        for (int r = 0; r < 16; r++) {
            ull x = lds64(xb + r * 128 + k);
            acc[r]      = ffma2(x, w0, acc[r]);
            acc[16 + r] = ffma2(x, w1, acc[16 + r]);
        }
    }
#pragma unroll
    for (int r = 0; r < 16; r++) {
        size_t row = (size_t)(row0 + rh * 16 + r) * 128;
        out[row + cp]      = hadd2(acc[r]);
        out[row + cp + 64] = hadd2(acc[16 + r]);
    }
}

// ---------------------------------------------------------------------------
// Q projection: 16 rows/block, 256 threads.
// ---------------------------------------------------------------------------
__global__ __launch_bounds__(256) void q_proj(const float* __restrict__ last,
                                              const float* __restrict__ attr,
                                              const float* __restrict__ Wq) {
    __shared__ float xs[16 * 132];
    int row0 = blockIdx.x * 16;
    int t = threadIdx.x;
#pragma unroll
    for (int i = t; i < 2048; i += 256) {
        int r = i >> 7, c = i & 127;
        xs[r * 132 + c] = last[(size_t)(row0 + r) * 128 + c];
    }
    if (t < 16) xs[t * 132 + 128] = attr[row0 + t];
    __syncthreads();

    int rh = t >> 7, col = t & 127;
    const float* xr = xs + rh * 8 * 132;
    float acc[8] = {0, 0, 0, 0, 0, 0, 0, 0};
#pragma unroll 4
    for (int in = 0; in < 129; in++) {
        float w = Wq[in * 128 + col];
#pragma unroll
        for (int r = 0; r < 8; r++) acc[r] += xr[r * 132 + in] * w;
    }
#pragma unroll
    for (int r = 0; r < 8; r++)
        g_Q[(size_t)(row0 + rh * 8 + r) * 128 + col] = acc[r];
}

// ---------------------------------------------------------------------------
// Fused attention + Wo + tanh scoring + final softmax.
// block = (b, 32-query tile), 256 threads, 512 blocks.
// Phase A: warp = head h, lane = query p. Lane loops over all n of chunk;
//   K/V LDS are full 32-lane broadcasts. No max tracking (bounded logits),
//   one exp per score, no cross-lane merges.
// smem floats: mh 4224 | inv 32 | out 4224 | work 19008  = 27488 (109952 B)
//   A: k0/k1 (32x132) | v0/v1 (32x132) | m0/m1 (32x33)
//   Wo stage: 16384 in work
//   B: enc0/enc1 (64x132)
// ---------------------------------------------------------------------------
__global__ __launch_bounds__(256, 2) void attn_kernel(
        const float* __restrict__ enc, const float* __restrict__ mask,
        const float* __restrict__ Wo, const float* __restrict__ bo,
        float* __restrict__ probs) {
    extern __shared__ float sm[];
    float* mh_s  = sm;
    float* inv_s = sm + 4224;
    float* out_s = sm + 4256;
    float* work  = sm + 8480;

    int t = threadIdx.x;
    int b = blockIdx.x >> 3;
    int p0 = (blockIdx.x & 7) * 32;
    int h = t >> 5, lane = t & 31;

    const float* Kb = g_K + (size_t)b * NN * 128;
    const float* Vb = g_V + (size_t)b * NN * 128;
    const float* Mb = mask + (size_t)(b * PP + p0) * NN;

    auto stageA = [&](int chunk) {
        int buf = chunk & 1;
        int base = chunk * 32;
        int nv = NN - base; if (nv > 32) nv = 32;
        float* kd = work + buf * 4224;
        float* vd = work + 8448 + buf * 4224;
        float* md = work + 16896 + buf * 1056;
#pragma unroll
        for (int j = 0; j < 4; j++) {
            int i = t + j * 256;
            int n = i >> 5, seg = i & 31;
            if (n < nv) {
                cp16(kd + n * 132 + seg * 4, Kb + (size_t)(base + n) * 128 + seg * 4);
                cp16(vd + n * 132 + seg * 4, Vb + (size_t)(base + n) * 128 + seg * 4);
            } else {
                sts128z(kd + n * 132 + seg * 4);
                sts128z(vd + n * 132 + seg * 4);
            }
        }
#pragma unroll
        for (int j = 0; j < 4; j++) {
            int i = t + j * 256;
            int p = i >> 5, n = i & 31;
            if (n < nv) cp4(md + p * 33 + n, Mb + (size_t)p * NN + base + n);
            else        sts32(md + p * 33 + n, -1e30f);
        }
    };
    auto stageB = [&](int chunk) {
        int buf = chunk & 1;
        int base = chunk * 64;
        int nv = NN - base; if (nv > 64) nv = 64;
        float* ed = work + buf * 8448;
        const float* Eb = enc + (size_t)b * NN * 128;
#pragma unroll
        for (int j = 0; j < 8; j++) {
            int i = t + j * 256;
            int n = i >> 5, seg = i & 31;
            if (n < nv)
                cp16(ed + n * 132 + seg * 4, Eb + (size_t)(base + n) * 128 + seg * 4);
        }
    };

    // q (0.25 prescaled) as 8 d-pairs
    ull qpk[8];
    {
        const float* qp = g_Q + (size_t)(b * PP + p0 + lane) * 128 + h * 16;
        ull c = pack2(0.25f, 0.25f);
#pragma unroll
        for (int j = 0; j < 4; j++) {
            ull a0, a1;
            ldg2x64(qp + 4 * j, a0, a1);
            qpk[2 * j]     = fmul2(a0, c);
            qpk[2 * j + 1] = fmul2(a1, c);
        }
    }

    float l = 0.f;
    ull acc[8];
#pragma unroll
    for (int j = 0; j < 8; j++) acc[j] = 0ull;

    stageA(0); cp_commit();
    stageA(1); cp_commit();

    // ---- phase A: 32 chunks of 32 keys ----
    for (int c = 0; c < 32; c++) {
        if (c == 31) cp_wait<0>(); else cp_wait<1>();
        __syncthreads();

        int buf = c & 1;
        const float* k_s    = work + buf * 4224;
        const float* v_s    = work + 8448 + buf * 4224;
        const float* mask_s = work + 16896 + buf * 1056 + lane * 33;

#pragma unroll 4
        for (int n = 0; n < 32; n++) {
            const float* kp = k_s + n * 132 + h * 16;
            ull k0, k1, k2, k3, k4, k5, k6, k7;
            lds2x64(kp,      k0, k1);
            lds2x64(kp + 4,  k2, k3);
            lds2x64(kp + 8,  k4, k5);
            lds2x64(kp + 12, k6, k7);
            ull d = fmul2(qpk[0], k0);
            d = ffma2(qpk[1], k1, d); d = ffma2(qpk[2], k2, d);
            d = ffma2(qpk[3], k3, d); d = ffma2(qpk[4], k4, d);
            d = ffma2(qpk[5], k5, d); d = ffma2(qpk[6], k6, d);
            d = ffma2(qpk[7], k7, d);
            float s = hadd2(d) + mask_s[n];
            s = fminf(fmaxf(s, -60.f), 60.f);
            float w = __expf(s);
            l += w;
            const float* vp = v_s + n * 132 + h * 16;
            ull v0, v1, v2, v3, v4, v5, v6, v7;
            lds2x64(vp,      v0, v1);
            lds2x64(vp + 4,  v2, v3);
            lds2x64(vp + 8,  v4, v5);
            lds2x64(vp + 12, v6, v7);
            ull ww = pack2(w, w);
            acc[0] = ffma2(ww, v0, acc[0]); acc[1] = ffma2(ww, v1, acc[1]);
            acc[2] = ffma2(ww, v2, acc[2]); acc[3] = ffma2(ww, v3, acc[3]);
            acc[4] = ffma2(ww, v4, acc[4]); acc[5] = ffma2(ww, v5, acc[5]);
            acc[6] = ffma2(ww, v6, acc[6]); acc[7] = ffma2(ww, v7, acc[7]);
        }
        __syncthreads();
        if (c + 2 < 32) { stageA(c + 2); cp_commit(); }
    }

    // finalize: out[p][h*16+d] = acc/l
    {
        float inv = 1.f / l;
        ull iv = pack2(inv, inv);
        float* op = out_s + lane * 132 + h * 16;
#pragma unroll
        for (int j = 0; j < 8; j++) sts64(op + 2 * j, fmul2(acc[j], iv));
    }
    __syncthreads();

    // stage Wo (64KB) into work
    {
        float* wd = work;
        const float4* Wo4 = (const float4*)Wo;
#pragma unroll
        for (int j = 0; j < 16; j++) {
            int i = t + j * 256;
            cp16(wd + i * 4, (const float*)(Wo4 + i));
        }
        cp_commit(); cp_wait<0>();
    }
    __syncthreads();

    // mh = out @ Wo + bo   (thread = 2p x 8e; Wo from smem)
    {
        int pg = t >> 4;            // 16 groups of 2p
        int eg = (t & 15) * 8;      // 8 e's
        const float* Wos = work;
        ull a0[4], a1[4];
        {
            ull b0, b1, b2, b3;
            ldg2x64(bo + eg, b0, b1);
            ldg2x64(bo + eg + 4, b2, b3);
            a0[0] = b0; a0[1] = b1; a0[2] = b2; a0[3] = b3;
            a1[0] = b0; a1[1] = b1; a1[2] = b2; a1[3] = b3;
        }
        const float* x0p = out_s + (2 * pg) * 132;
        const float* x1p = x0p + 132;
#pragma unroll 4
        for (int k = 0; k < 128; k++) {
            float x0 = x0p[k], x1 = x1p[k];
            ull xx0 = pack2(x0, x0), xx1 = pack2(x1, x1);
            const float* wp = Wos + k * 128 + eg;
            ull w0, w1, w2, w3;
            lds2x64(wp, w0, w1);
            lds2x64(wp + 4, w2, w3);
            a0[0] = ffma2(xx0, w0, a0[0]); a0[1] = ffma2(xx0, w1, a0[1]);
            a0[2] = ffma2(xx0, w2, a0[2]); a0[3] = ffma2(xx0, w3, a0[3]);
            a1[0] = ffma2(xx1, w0, a1[0]); a1[1] = ffma2(xx1, w1, a1[1]);
            a1[2] = ffma2(xx1, w2, a1[2]); a1[3] = ffma2(xx1, w3, a1[3]);
        }
        float* m0 = mh_s + (2 * pg) * 132 + eg;
        float* m1 = m0 + 132;
#pragma unroll
        for (int j = 0; j < 4; j++) { sts64(m0 + 2 * j, a0[j]); sts64(m1 + 2 * j, a1[j]); }
    }
    __syncthreads();   // Wo reads done; work free for enc

    stageB(0); cp_commit();
    stageB(1); cp_commit();

    // ---- phase B: 16 chunks of 64 nodes; thread = 4p x 2n ----
    int pq = t >> 5;            // warp id -> 4 p's
    int nh = t & 31;            // n, n+32
    float rs[4] = {0.f, 0.f, 0.f, 0.f};
    float* pout = probs + (size_t)(b * PP + p0) * NN;
    const float inv_se = 0.08838834764831845f;
    const float* mrow = mh_s + (4 * pq) * 132;

    for (int c = 0; c < 16; c++) {
        if (c == 15) cp_wait<0>(); else cp_wait<1>();
        __syncthreads();

        int buf = c & 1;
        int base = c * 64;
        int nv = NN - base; if (nv > 64) nv = 64;
        const float* e_s = work + buf * 8448;
        const float* e0p = e_s + nh * 132;
        const float* e1p = e_s + (nh + 32) * 132;

        ull a[4][2];
#pragma unroll
        for (int pp = 0; pp < 4; pp++) { a[pp][0] = 0ull; a[pp][1] = 0ull; }

#pragma unroll 4
        for (int k = 0; k < 128; k += 4) {
            ull e00, e01, e10, e11;
            lds2x64(e0p + k, e00, e01);
            lds2x64(e1p + k, e10, e11);
#pragma unroll
            for (int pp = 0; pp < 4; pp++) {
                ull m0, m1;
                lds2x64(mrow + pp * 132 + k, m0, m1);
                a[pp][0] = ffma2(m0, e00, a[pp][0]);
                a[pp][0] = ffma2(m1, e01, a[pp][0]);
                a[pp][1] = ffma2(m0, e10, a[pp][1]);
                a[pp][1] = ffma2(m1, e11, a[pp][1]);
            }
        }
#pragma unroll
        for (int j = 0; j < 2; j++) {
            int n = nh + 32 * j;
            if (n < nv) {
#pragma unroll
                for (int pp = 0; pp < 4; pp++) {
                    int p = 4 * pq + pp;
                    float sd = hadd2(a[pp][j]);
                    float x = sd * inv_se;
                    x = fminf(fmaxf(x, -30.f), 30.f);
                    float ex = __expf(-2.f * x);
                    float th = __fdividef(1.f - ex, 1.f + ex);
                    float lg = 10.f * th + Mb[(size_t)p * NN + base + n];
                    float w = __expf(lg - 10.f);
                    rs[pp] += w;
                    pout[(size_t)p * NN + base + n] = w;
                }
            }
        }
        __syncthreads();
        if (c + 2 < 16) { stageB(c + 2); cp_commit(); }
    }

    // warp-reduce row sums (each warp owns its 4 p's entirely)
#pragma unroll
    for (int off = 16; off; off >>= 1) {
#pragma unroll
        for (int pp = 0; pp < 4; pp++)
            rs[pp] += __shfl_xor_sync(0xFFFFFFFFu, rs[pp], off);
    }
    if (nh == 0) {
#pragma unroll
        for (int pp = 0; pp < 4; pp++) inv_s[4 * pq + pp] = 1.f / rs[pp];
    }
    __syncthreads();
#pragma unroll
    for (int p = 0; p < 32; p++) {
        float ivp = inv_s[p];
        for (int i = t; i < NN; i += 256)
            pout[(size_t)p * NN + i] *= ivp;
    }
}

// ---------------------------------------------------------------------------
extern "C" void kernel_launch(void* const* d_in, const int* in_sizes, int n_in,
                              void* d_out, int out_size) {
    const float* enc  = (const float*)d_in[0];
    const float* last = (const float*)d_in[1];
    const float* attr = (const float*)d_in[2];
    const float* mask = (const float*)d_in[3];
    const float* Wq   = (const float*)d_in[4];
    const float* Wk   = (const float*)d_in[5];
    const float* Wv   = (const float*)d_in[6];
    const float* Wo   = (const float*)d_in[7];
    const float* bo   = (const float*)d_in[8];
    float* out = (float*)d_out;

    cudaFuncSetAttribute(attn_kernel,
                         cudaFuncAttributeMaxDynamicSharedMemorySize, 109952);

    kv_proj<<<2000, 256>>>(enc, Wk, Wv);
    q_proj<<<1024, 256>>>(last, attr, Wq);
    attn_kernel<<<512, 256, 109952>>>(enc, mask, Wo, bo, out);
}